// round 14
// baseline (speedup 1.0000x reference)
#include <cuda_runtime.h>
#include <cuda_bf16.h>
#include <float.h>
#include <stdint.h>

// ---------------------------------------------------------------------------
// MVCNN: ragged max-pool -> 3-layer MLP.
// GEMMs via mma.sync.m16n8k16 (bf16 hi/lo split, f32 acc).
// R14 = R13 + ksplit 16 on layers 1/2 (512 CTAs -> 3.4 CTAs/SM; the
//       launch_bounds(256,3) headroom was unreachable with 256 CTAs).
// ---------------------------------------------------------------------------

#define BATCH 64
#define DIM   4096
#define VIEWS 256
#define OUTN  1000

__device__ __align__(256) __nv_bfloat16 g_actH[BATCH * DIM];
__device__ __align__(256) __nv_bfloat16 g_actL[BATCH * DIM];
__device__ __align__(256) float g_part[16][DIM * BATCH];  // [ksplit][feat][batch]

// ---------------------------------------------------------------------------
// helpers
// ---------------------------------------------------------------------------
__device__ __forceinline__ uint32_t smem_u32(const void* p) {
    uint32_t a;
    asm("{ .reg .u64 t; cvta.to.shared.u64 t, %1; cvt.u32.u64 %0, t; }"
        : "=r"(a) : "l"(p));
    return a;
}
__device__ __forceinline__ void cp16(uint32_t dst, const void* src) {
    asm volatile("cp.async.cg.shared.global [%0], [%1], 16;"
                 :: "r"(dst), "l"(src));
}
__device__ __forceinline__ void cp_commit() {
    asm volatile("cp.async.commit_group;" ::: "memory");
}
template<int N> __device__ __forceinline__ void cp_wait() {
    asm volatile("cp.async.wait_group %0;" :: "n"(N) : "memory");
}
__device__ __forceinline__ void ldsm4(uint32_t* r, uint32_t a) {
    asm volatile("ldmatrix.sync.aligned.m8n8.x4.shared.b16 {%0,%1,%2,%3}, [%4];"
        : "=r"(r[0]), "=r"(r[1]), "=r"(r[2]), "=r"(r[3]) : "r"(a));
}
__device__ __forceinline__ void ldsm4t(uint32_t* r, uint32_t a) {
    asm volatile("ldmatrix.sync.aligned.m8n8.x4.trans.shared.b16 {%0,%1,%2,%3}, [%4];"
        : "=r"(r[0]), "=r"(r[1]), "=r"(r[2]), "=r"(r[3]) : "r"(a));
}
__device__ __forceinline__ void mma16816(float* c, const uint32_t* a,
                                         uint32_t b0, uint32_t b1) {
    asm volatile(
        "mma.sync.aligned.m16n8k16.row.col.f32.bf16.bf16.f32 "
        "{%0,%1,%2,%3}, {%4,%5,%6,%7}, {%8,%9}, {%0,%1,%2,%3};"
        : "+f"(c[0]), "+f"(c[1]), "+f"(c[2]), "+f"(c[3])
        : "r"(a[0]), "r"(a[1]), "r"(a[2]), "r"(a[3]), "r"(b0), "r"(b1));
}
__device__ __forceinline__ void stW_hilo(uint32_t baseH, uint32_t baseL,
                                         uint32_t off, float4 f) {
    uint32_t h01, h23, l01, l23;
    asm("cvt.rn.satfinite.bf16x2.f32 %0, %1, %2;" : "=r"(h01) : "f"(f.y), "f"(f.x));
    asm("cvt.rn.satfinite.bf16x2.f32 %0, %1, %2;" : "=r"(h23) : "f"(f.w), "f"(f.z));
    float l0 = f.x - __uint_as_float(h01 << 16);
    float l1 = f.y - __uint_as_float(h01 & 0xffff0000u);
    float l2 = f.z - __uint_as_float(h23 << 16);
    float l3 = f.w - __uint_as_float(h23 & 0xffff0000u);
    asm("cvt.rn.satfinite.bf16x2.f32 %0, %1, %2;" : "=r"(l01) : "f"(l1), "f"(l0));
    asm("cvt.rn.satfinite.bf16x2.f32 %0, %1, %2;" : "=r"(l23) : "f"(l3), "f"(l2));
    asm volatile("st.shared.v2.b32 [%0], {%1,%2};"
                 :: "r"(baseH + off), "r"(h01), "r"(h23));
    asm volatile("st.shared.v2.b32 [%0], {%1,%2};"
                 :: "r"(baseL + off), "r"(l01), "r"(l23));
}

// ---------------------------------------------------------------------------
// Ragged max-pool -> bf16 hi/lo activations  act[batch][feat]  (R12-proven)
// ---------------------------------------------------------------------------
__global__ void pool_kernel(const float* __restrict__ x,
                            const float* __restrict__ xa,
                            const int*   __restrict__ lens,
                            __nv_bfloat16* __restrict__ actH,
                            __nv_bfloat16* __restrict__ actL)
{
    const int gw   = (blockIdx.x * blockDim.x + threadIdx.x) >> 5;
    const int lane = threadIdx.x & 31;
    const int rg   = lane >> 3;
    const int sub  = lane & 7;
    const int row  = gw * 4 + rg;
    if (row >= BATCH * DIM) return;
    const int b = row >> 12;
    const int d = row & 4095;

    const float* src = (d < 2048)
        ? (x  + ((size_t)(b * 2048 + d)        ) * VIEWS)
        : (xa + ((size_t)(b * 2048 + (d - 2048))) * VIEWS);

    int len = lens[b];
    len = max(1, min(len, VIEWS));

    float m = -FLT_MAX;
    #pragma unroll
    for (int i = 0; i < 8; ++i) {
        const int v0 = sub * 4 + i * 32;
        if (v0 < len) {
            float4 v = *reinterpret_cast<const float4*>(src + v0);
            m = fmaxf(m, v.x);
            if (v0 + 1 < len) m = fmaxf(m, v.y);
            if (v0 + 2 < len) m = fmaxf(m, v.z);
            if (v0 + 3 < len) m = fmaxf(m, v.w);
        }
    }
    #pragma unroll
    for (int o = 4; o; o >>= 1)
        m = fmaxf(m, __shfl_xor_sync(0xffffffffu, m, o));

    if (sub == 0) {
        __nv_bfloat16 h = __float2bfloat16(m);
        actH[row] = h;
        actL[row] = __float2bfloat16(m - __bfloat162float(h));
    }
}

// ---------------------------------------------------------------------------
// L1/L2 GEMM: k32 stages, NT=128, 3 CTAs/SM, ksplit 16.
//   grid (32, 16): n128-tiles x ksplit; kchunk 256 -> NST=8 k32-stages.
// ---------------------------------------------------------------------------
#define STG32     32768
#define O32_WL    8192
#define O32_AH    16384
#define O32_AL    24576
#define SMEM_K32  (2 * STG32 + 1024)

__global__ void __launch_bounds__(256, 3) gemm_k32(
    const float* __restrict__ W,
    const __nv_bfloat16* __restrict__ actH,
    const __nv_bfloat16* __restrict__ actL,
    float* __restrict__ partBase)
{
    constexpr int N   = DIM;
    constexpr int NST = 8;
    constexpr int KCH = NST * 32;     // 256

    extern __shared__ char smraw[];
    const uint32_t s0 = (smem_u32(smraw) + 1023) & ~1023u;
    const int tid = threadIdx.x;
    const int warp = tid >> 5, lane = tid & 31;
    const int warpM = warp & 1;
    const int warpN = warp >> 1;
    const int n0 = blockIdx.x * 128;
    const int kb = blockIdx.y * KCH;
    float* part = partBase + (size_t)blockIdx.y * (DIM * BATCH);

    // W fp32 load: 8 threads per k-row (32 rows), 16 floats each
    const int wk = tid >> 3;
    const int wn = (tid & 7) * 16;
    const float* wgp = W + (size_t)(kb + wk) * N + n0 + wn;
    const uint32_t wswz = (uint32_t)(wk & 7) << 4;
    const uint32_t wsrow = (uint32_t)wk * 256;

    // A cp.async: 4 threads per m-row, 1 x 16B per polarity
    const int am = tid >> 2;
    const int akc = (tid & 3) * 8;
    const __nv_bfloat16* agpH = actH + (size_t)am * DIM + kb + akc;
    const __nv_bfloat16* agpL = actL + (size_t)am * DIM + kb + akc;
    const uint32_t aoff = (uint32_t)am * 128
                        + (((uint32_t)(akc * 2)) ^ ((uint32_t)(am & 7) << 4));

    const uint32_t arow = (lane & 7) + ((lane >> 3) & 1) * 8;
    const uint32_t ak2  = ((lane >> 4) & 1) * 16;
    const uint32_t aswz = (uint32_t)(lane & 7) << 4;

    const uint32_t brow  = (lane & 7) + ((lane >> 3) & 1) * 8;
    const uint32_t bhalf = ((lane >> 4) & 1) * 8;

    float acc[2][4][4];
    #pragma unroll
    for (int i = 0; i < 2; ++i)
        #pragma unroll
        for (int j = 0; j < 4; ++j)
            #pragma unroll
            for (int q = 0; q < 4; ++q) acc[i][j][q] = 0.f;

    float4 w0[2];

    auto ldWj = [&](int s, int j) -> float4 {
        return *reinterpret_cast<const float4*>(
            wgp + (size_t)(s * 32) * N + j * 4);
    };
    auto loadW0 = [&](int s) {
        w0[0] = ldWj(s, 0);
        w0[1] = ldWj(s, 1);
    };
    auto storeW = [&](int s, int buf) {
        const uint32_t bH = s0 + buf * STG32 + wsrow;
        const uint32_t bL = bH + O32_WL;
        float4 w2 = ldWj(s, 2);
        float4 w3 = ldWj(s, 3);
        stW_hilo(bH, bL, ((uint32_t)((wn + 0) * 2)) ^ wswz, w0[0]);
        stW_hilo(bH, bL, ((uint32_t)((wn + 4) * 2)) ^ wswz, w0[1]);
        stW_hilo(bH, bL, ((uint32_t)((wn + 8) * 2)) ^ wswz, w2);
        stW_hilo(bH, bL, ((uint32_t)((wn + 12) * 2)) ^ wswz, w3);
    };
    auto issueA = [&](int s, int buf) {
        const uint32_t base = s0 + buf * STG32;
        cp16(base + O32_AH + aoff, agpH + s * 32);
        cp16(base + O32_AL + aoff, agpL + s * 32);
        cp_commit();
    };
    auto compute = [&](int buf) {
        const uint32_t base = s0 + buf * STG32;
        #pragma unroll
        for (int ks = 0; ks < 2; ++ks) {
            uint32_t bh[2][4], bl[2][4];
            #pragma unroll
            for (int nt = 0; nt < 2; ++nt) {
                uint32_t bcol = ((uint32_t)((warpN * 32 + nt * 16 + bhalf) * 2))
                              ^ ((uint32_t)(lane & 7) << 4);
                uint32_t boff = (uint32_t)(ks * 16 + brow) * 256 + bcol;
                ldsm4t(bh[nt], base + boff);
                ldsm4t(bl[nt], base + O32_WL + boff);
            }
            const uint32_t kx = (uint32_t)(ks * 32 + ak2) ^ aswz;
            #pragma unroll
            for (int mt = 0; mt < 2; ++mt) {
                const uint32_t ar = (uint32_t)(warpM * 32 + mt * 16 + arow) * 128
                                  + kx;
                uint32_t ah[4], al[4];
                ldsm4(ah, base + O32_AH + ar);
                ldsm4(al, base + O32_AL + ar);
                #pragma unroll
                for (int nt = 0; nt < 2; ++nt) {
                    mma16816(acc[mt][nt * 2 + 0], ah, bh[nt][0], bh[nt][1]);
                    mma16816(acc[mt][nt * 2 + 1], ah, bh[nt][2], bh[nt][3]);
                    mma16816(acc[mt][nt * 2 + 0], al, bh[nt][0], bh[nt][1]);
                    mma16816(acc[mt][nt * 2 + 1], al, bh[nt][2], bh[nt][3]);
                    mma16816(acc[mt][nt * 2 + 0], ah, bl[nt][0], bl[nt][1]);
                    mma16816(acc[mt][nt * 2 + 1], ah, bl[nt][2], bl[nt][3]);
                }
            }
        }
    };

    issueA(0, 0);
    loadW0(0);
    #pragma unroll
    for (int s = 0; s < NST; ++s) {
        const int buf = s & 1;
        storeW(s, buf);
        if (s + 1 < NST) loadW0(s + 1);
        cp_wait<0>();
        __syncthreads();
        if (s + 1 < NST) issueA(s + 1, buf ^ 1);
        compute(buf);
    }

    const int g = lane >> 2, tg = lane & 3;
    #pragma unroll
    for (int mt = 0; mt < 2; ++mt)
        #pragma unroll
        for (int nt = 0; nt < 4; ++nt) {
            int feat = n0 + warpN * 32 + nt * 8 + tg * 2;
            int bat  = warpM * 32 + mt * 16 + g;
            float* p = part + (size_t)feat * 64 + bat;
            p[0]      = acc[mt][nt][0];
            p[64]     = acc[mt][nt][1];
            p[8]      = acc[mt][nt][2];
            p[64 + 8] = acc[mt][nt][3];
        }
}

// ---------------------------------------------------------------------------
// L3 GEMM (R12-proven): k64 stages, NT=64, NST=4
// ---------------------------------------------------------------------------
#define RB64      128
#define WB64      (64 * RB64)
#define O64_WL    WB64
#define O64_AH    (2 * WB64)
#define O64_AL    (2 * WB64 + 8192)
#define STG64     (2 * WB64 + 16384)
#define SMEM_K64  (2 * STG64 + 1024)

__global__ void __launch_bounds__(256) gemm_l3(
    const float* __restrict__ W, int N,
    const __nv_bfloat16* __restrict__ actH,
    const __nv_bfloat16* __restrict__ actL,
    float* __restrict__ partBase)
{
    constexpr int NST = 4;
    extern __shared__ char smraw[];
    const uint32_t s0 = (smem_u32(smraw) + 1023) & ~1023u;
    const int tid = threadIdx.x;
    const int warp = tid >> 5, lane = tid & 31;
    const int warpM = warp & 1;
    const int warpN = warp >> 1;
    const int n0 = blockIdx.x * 64;
    const int kb = blockIdx.y * 256;
    float* part = partBase + (size_t)blockIdx.y * (DIM * BATCH);

    const int wk = tid >> 2;
    const int wn = (tid & 3) * 16;
    const float* wgp = W + (size_t)(kb + wk) * N + n0 + wn;
    const uint32_t wswz = (uint32_t)(wk & 7) << 4;
    const uint32_t wsrow = (uint32_t)wk * RB64;

    const int am = tid >> 2;
    const int akb = (tid & 3) * 16;
    const __nv_bfloat16* agpH = actH + (size_t)am * DIM + kb + akb;
    const __nv_bfloat16* agpL = actL + (size_t)am * DIM + kb + akb;
    uint32_t aoffc[2];
    #pragma unroll
    for (int c = 0; c < 2; ++c)
        aoffc[c] = (uint32_t)am * 128
                 + (((uint32_t)(akb * 2 + c * 16)) ^ ((uint32_t)(am & 7) << 4));

    const uint32_t arow = (lane & 7) + ((lane >> 3) & 1) * 8;
    const uint32_t ak2  = ((lane >> 4) & 1) * 16;
    const uint32_t aswz = (uint32_t)(lane & 7) << 4;

    const uint32_t brow  = (lane & 7) + ((lane >> 3) & 1) * 8;
    const uint32_t bhalf = ((lane >> 4) & 1) * 8;

    float acc[2][2][4];
    #pragma unroll
    for (int i = 0; i < 2; ++i)
        #pragma unroll
        for (int j = 0; j < 2; ++j)
            #pragma unroll
            for (int q = 0; q < 4; ++q) acc[i][j][q] = 0.f;

    float4 wreg[4];

    auto loadW = [&](int s) {
        const float* p = wgp + (size_t)s * 64 * N;
        #pragma unroll
        for (int j = 0; j < 4; ++j) {
            int col = n0 + wn + j * 4;
            if (col + 3 < N) {
                wreg[j] = *reinterpret_cast<const float4*>(p + j * 4);
            } else {
                float4 v;
                v.x = (col + 0 < N) ? p[j * 4 + 0] : 0.f;
                v.y = (col + 1 < N) ? p[j * 4 + 1] : 0.f;
                v.z = (col + 2 < N) ? p[j * 4 + 2] : 0.f;
                v.w = (col + 3 < N) ? p[j * 4 + 3] : 0.f;
                wreg[j] = v;
            }
        }
    };
    auto storeW = [&](int buf) {
        const uint32_t bH = s0 + buf * STG64 + wsrow;
        const uint32_t bL = bH + O64_WL;
        #pragma unroll
        for (int j = 0; j < 4; ++j)
            stW_hilo(bH, bL, ((uint32_t)((wn + j * 4) * 2)) ^ wswz, wreg[j]);
    };
    auto issueA = [&](int s, int buf) {
        const uint32_t base = s0 + buf * STG64;
        #pragma unroll
        for (int c = 0; c < 2; ++c) {
            cp16(base + O64_AH + aoffc[c], agpH + s * 64 + c * 8);
            cp16(base + O64_AL + aoffc[c], agpL + s * 64 + c * 8);
        }
        cp_commit();
    };
    auto compute = [&](int buf) {
        const uint32_t base = s0 + buf * STG64;
        #pragma unroll
        for (int ks = 0; ks < 4; ++ks) {
            uint32_t bh[4], bl[4];
            uint32_t bcol = ((uint32_t)((warpN * 16 + bhalf) * 2))
                          ^ ((uint32_t)(lane & 7) << 4);
            uint32_t boff = (uint32_t)(ks * 16 + brow) * RB64 + bcol;
            ldsm4t(bh, base + boff);
            ldsm4t(bl, base + O64_WL + boff);
            const uint32_t kx = (uint32_t)(ks * 32 + ak2) ^ aswz;
            #pragma unroll
            for (int mt = 0; mt < 2; ++mt) {
                const uint32_t ar = (uint32_t)(warpM * 32 + mt * 16 + arow) * 128
                                  + kx;
                uint32_t ah[4], al[4];
                ldsm4(ah, base + O64_AH + ar);
                ldsm4(al, base + O64_AL + ar);
                mma16816(acc[mt][0], ah, bh[0], bh[1]);
                mma16816(acc[mt][1], ah, bh[2], bh[3]);
                mma16816(acc[mt][0], al, bh[0], bh[1]);
                mma16816(acc[mt][1], al, bh[2], bh[3]);
                mma16816(acc[mt][0], ah, bl[0], bl[1]);
                mma16816(acc[mt][1], ah, bl[2], bl[3]);
            }
        }
    };

    issueA(0, 0);
    loadW(0);
    #pragma unroll
    for (int s = 0; s < NST; ++s) {
        const int buf = s & 1;
        storeW(buf);
        if (s + 1 < NST) loadW(s + 1);
        cp_wait<0>();
        __syncthreads();
        if (s + 1 < NST) issueA(s + 1, buf ^ 1);
        compute(buf);
    }

    const int g = lane >> 2, tg = lane & 3;
    #pragma unroll
    for (int mt = 0; mt < 2; ++mt)
        #pragma unroll
        for (int nt = 0; nt < 2; ++nt) {
            int feat = n0 + warpN * 16 + nt * 8 + tg * 2;
            int bat  = warpM * 32 + mt * 16 + g;
            float* p = part + (size_t)feat * 64 + bat;
            p[0]      = acc[mt][nt][0];
            p[64]     = acc[mt][nt][1];
            p[8]      = acc[mt][nt][2];
            p[64 + 8] = acc[mt][nt][3];
        }
}

// ---------------------------------------------------------------------------
// Coalesced transpose-reduces (R11-proven; 16 splits)
// ---------------------------------------------------------------------------
__global__ void __launch_bounds__(256) reduce_bias_relu_t(
    const float* __restrict__ bias,
    __nv_bfloat16* __restrict__ actH,
    __nv_bfloat16* __restrict__ actL)
{
    __shared__ __nv_bfloat16 tH[16][66], tL[16][66];
    const int t = threadIdx.x;
    const int mb = blockIdx.x * 16;

    {
        const int n  = t & 63;
        const int ml = t >> 6;
        #pragma unroll
        for (int j = 0; j < 4; ++j) {
            int mloc = ml * 4 + j;
            int m = mb + mloc;
            float s = bias[m];
            #pragma unroll
            for (int z = 0; z < 16; ++z)
                s += g_part[z][(size_t)m * 64 + n];
            s = fmaxf(s, 0.f);
            __nv_bfloat16 h = __float2bfloat16(s);
            tH[mloc][n] = h;
            tL[mloc][n] = __float2bfloat16(s - __bfloat162float(h));
        }
    }
    __syncthreads();
    {
        const int m2 = t & 15;
        const int nl = t >> 4;
        #pragma unroll
        for (int j = 0; j < 4; ++j) {
            int n2 = nl * 4 + j;
            size_t o = (size_t)n2 * DIM + mb + m2;
            actH[o] = tH[m2][n2];
            actL[o] = tL[m2][n2];
        }
    }
}

__global__ void __launch_bounds__(256) reduce_out_t(
    const float* __restrict__ b3,
    float* __restrict__ out)
{
    __shared__ float tO[8][66];
    const int t = threadIdx.x;
    const int mb = blockIdx.x * 8;

    #pragma unroll
    for (int i = t; i < 512; i += 256) {
        int mloc = i >> 6;
        int n = i & 63;
        int m = mb + mloc;
        float s = b3[m];
        #pragma unroll
        for (int z = 0; z < 16; ++z)
            s += g_part[z][(size_t)m * 64 + n];
        tO[mloc][n] = s;
    }
    __syncthreads();
    #pragma unroll
    for (int i = t; i < 512; i += 256) {
        int mloc = i & 7;
        int n2 = i >> 3;
        out[(size_t)n2 * OUTN + mb + mloc] = tO[mloc][n2];
    }
}

// ---------------------------------------------------------------------------
// launch
// ---------------------------------------------------------------------------
extern "C" void kernel_launch(void* const* d_in, const int* in_sizes, int n_in,
                              void* d_out, int out_size)
{
    const float* x    = (const float*)d_in[0];
    const float* xa   = (const float*)d_in[1];
    const int*   lens = (const int*)  d_in[2];
    const float* w1   = (const float*)d_in[3];
    const float* b1   = (const float*)d_in[4];
    const float* w2   = (const float*)d_in[5];
    const float* b2   = (const float*)d_in[6];
    const float* w3   = (const float*)d_in[7];
    const float* b3   = (const float*)d_in[8];
    float* out = (float*)d_out;

    __nv_bfloat16 *actH, *actL;
    float* part;
    cudaGetSymbolAddress((void**)&actH, g_actH);
    cudaGetSymbolAddress((void**)&actL, g_actL);
    cudaGetSymbolAddress((void**)&part, g_part);

    cudaFuncSetAttribute(gemm_k32,
                         cudaFuncAttributeMaxDynamicSharedMemorySize, SMEM_K32);
    cudaFuncSetAttribute(gemm_l3,
                         cudaFuncAttributeMaxDynamicSharedMemorySize, SMEM_K64);

    // 1) pool -> act hi/lo (4 rows per warp, MLP 8)
    {
        int warps = (BATCH * DIM) / 4;
        int blocks = (warps * 32 + 255) / 256;
        pool_kernel<<<blocks, 256>>>(x, xa, lens, actH, actL);
    }
    // 2) layer 1: 32 n128-tiles x ksplit 16 (kchunk 256, 8 k32-stages)
    gemm_k32<<<dim3(32, 16), 256, SMEM_K32>>>(w1, actH, actL, part);
    reduce_bias_relu_t<<<256, 256>>>(b1, actH, actL);
    // 3) layer 2
    gemm_k32<<<dim3(32, 16), 256, SMEM_K32>>>(w2, actH, actL, part);
    reduce_bias_relu_t<<<256, 256>>>(b2, actH, actL);
    // 4) layer 3: 16 n64-tiles x ksplit 16 (kchunk 256, 4 k64-stages)
    gemm_l3<<<dim3(16, 16), 256, SMEM_K64>>>(w3, OUTN, actH, actL, part);
    reduce_out_t<<<125, 256>>>(b3, out);
}

// round 15
// speedup vs baseline: 1.1129x; 1.1129x over previous
#include <cuda_runtime.h>
#include <cuda_bf16.h>
#include <float.h>
#include <stdint.h>

// ---------------------------------------------------------------------------
// MVCNN: ragged max-pool -> 3-layer MLP.
// GEMMs via mma.sync.m16n8k16 (bf16 hi/lo split, f32 acc).
// R15 = R13 (proven 117.5) + FULL next-stage W register prefetch: storeW is
//       pure cvt+STS (no LDG dependence); DRAM latency covered by compute(s).
//       launch_bounds(256,2) (R14 proved extra occupancy doesn't help).
// ---------------------------------------------------------------------------

#define BATCH 64
#define DIM   4096
#define VIEWS 256
#define OUTN  1000

__device__ __align__(256) __nv_bfloat16 g_actH[BATCH * DIM];
__device__ __align__(256) __nv_bfloat16 g_actL[BATCH * DIM];
__device__ __align__(256) float g_part[16][DIM * BATCH];  // [ksplit][feat][batch]

// ---------------------------------------------------------------------------
// helpers
// ---------------------------------------------------------------------------
__device__ __forceinline__ uint32_t smem_u32(const void* p) {
    uint32_t a;
    asm("{ .reg .u64 t; cvta.to.shared.u64 t, %1; cvt.u32.u64 %0, t; }"
        : "=r"(a) : "l"(p));
    return a;
}
__device__ __forceinline__ void cp16(uint32_t dst, const void* src) {
    asm volatile("cp.async.cg.shared.global [%0], [%1], 16;"
                 :: "r"(dst), "l"(src));
}
__device__ __forceinline__ void cp_commit() {
    asm volatile("cp.async.commit_group;" ::: "memory");
}
template<int N> __device__ __forceinline__ void cp_wait() {
    asm volatile("cp.async.wait_group %0;" :: "n"(N) : "memory");
}
__device__ __forceinline__ void ldsm4(uint32_t* r, uint32_t a) {
    asm volatile("ldmatrix.sync.aligned.m8n8.x4.shared.b16 {%0,%1,%2,%3}, [%4];"
        : "=r"(r[0]), "=r"(r[1]), "=r"(r[2]), "=r"(r[3]) : "r"(a));
}
__device__ __forceinline__ void ldsm4t(uint32_t* r, uint32_t a) {
    asm volatile("ldmatrix.sync.aligned.m8n8.x4.trans.shared.b16 {%0,%1,%2,%3}, [%4];"
        : "=r"(r[0]), "=r"(r[1]), "=r"(r[2]), "=r"(r[3]) : "r"(a));
}
__device__ __forceinline__ void mma16816(float* c, const uint32_t* a,
                                         uint32_t b0, uint32_t b1) {
    asm volatile(
        "mma.sync.aligned.m16n8k16.row.col.f32.bf16.bf16.f32 "
        "{%0,%1,%2,%3}, {%4,%5,%6,%7}, {%8,%9}, {%0,%1,%2,%3};"
        : "+f"(c[0]), "+f"(c[1]), "+f"(c[2]), "+f"(c[3])
        : "r"(a[0]), "r"(a[1]), "r"(a[2]), "r"(a[3]), "r"(b0), "r"(b1));
}
__device__ __forceinline__ void stW_hilo(uint32_t baseH, uint32_t baseL,
                                         uint32_t off, float4 f) {
    uint32_t h01, h23, l01, l23;
    asm("cvt.rn.satfinite.bf16x2.f32 %0, %1, %2;" : "=r"(h01) : "f"(f.y), "f"(f.x));
    asm("cvt.rn.satfinite.bf16x2.f32 %0, %1, %2;" : "=r"(h23) : "f"(f.w), "f"(f.z));
    float l0 = f.x - __uint_as_float(h01 << 16);
    float l1 = f.y - __uint_as_float(h01 & 0xffff0000u);
    float l2 = f.z - __uint_as_float(h23 << 16);
    float l3 = f.w - __uint_as_float(h23 & 0xffff0000u);
    asm("cvt.rn.satfinite.bf16x2.f32 %0, %1, %2;" : "=r"(l01) : "f"(l1), "f"(l0));
    asm("cvt.rn.satfinite.bf16x2.f32 %0, %1, %2;" : "=r"(l23) : "f"(l3), "f"(l2));
    asm volatile("st.shared.v2.b32 [%0], {%1,%2};"
                 :: "r"(baseH + off), "r"(h01), "r"(h23));
    asm volatile("st.shared.v2.b32 [%0], {%1,%2};"
                 :: "r"(baseL + off), "r"(l01), "r"(l23));
}

// ---------------------------------------------------------------------------
// Ragged max-pool -> bf16 hi/lo activations  act[batch][feat]  (R12-proven)
// ---------------------------------------------------------------------------
__global__ void pool_kernel(const float* __restrict__ x,
                            const float* __restrict__ xa,
                            const int*   __restrict__ lens,
                            __nv_bfloat16* __restrict__ actH,
                            __nv_bfloat16* __restrict__ actL)
{
    const int gw   = (blockIdx.x * blockDim.x + threadIdx.x) >> 5;
    const int lane = threadIdx.x & 31;
    const int rg   = lane >> 3;
    const int sub  = lane & 7;
    const int row  = gw * 4 + rg;
    if (row >= BATCH * DIM) return;
    const int b = row >> 12;
    const int d = row & 4095;

    const float* src = (d < 2048)
        ? (x  + ((size_t)(b * 2048 + d)        ) * VIEWS)
        : (xa + ((size_t)(b * 2048 + (d - 2048))) * VIEWS);

    int len = lens[b];
    len = max(1, min(len, VIEWS));

    float m = -FLT_MAX;
    #pragma unroll
    for (int i = 0; i < 8; ++i) {
        const int v0 = sub * 4 + i * 32;
        if (v0 < len) {
            float4 v = *reinterpret_cast<const float4*>(src + v0);
            m = fmaxf(m, v.x);
            if (v0 + 1 < len) m = fmaxf(m, v.y);
            if (v0 + 2 < len) m = fmaxf(m, v.z);
            if (v0 + 3 < len) m = fmaxf(m, v.w);
        }
    }
    #pragma unroll
    for (int o = 4; o; o >>= 1)
        m = fmaxf(m, __shfl_xor_sync(0xffffffffu, m, o));

    if (sub == 0) {
        __nv_bfloat16 h = __float2bfloat16(m);
        actH[row] = h;
        actL[row] = __float2bfloat16(m - __bfloat162float(h));
    }
}

// ---------------------------------------------------------------------------
// L1/L2 GEMM: k32 stages, NT=128, ksplit 8 (R13 grid), FULL W prefetch.
//   grid (32, 8): n128-tiles x ksplit; kchunk 512 -> NST=16 k32-stages.
// ---------------------------------------------------------------------------
#define STG32     32768
#define O32_WL    8192
#define O32_AH    16384
#define O32_AL    24576
#define SMEM_K32  (2 * STG32 + 1024)

__global__ void __launch_bounds__(256, 2) gemm_k32(
    const float* __restrict__ W,
    const __nv_bfloat16* __restrict__ actH,
    const __nv_bfloat16* __restrict__ actL,
    float* __restrict__ partBase)
{
    constexpr int N   = DIM;
    constexpr int NST = 16;
    constexpr int KCH = NST * 32;     // 512

    extern __shared__ char smraw[];
    const uint32_t s0 = (smem_u32(smraw) + 1023) & ~1023u;
    const int tid = threadIdx.x;
    const int warp = tid >> 5, lane = tid & 31;
    const int warpM = warp & 1;
    const int warpN = warp >> 1;
    const int n0 = blockIdx.x * 128;
    const int kb = blockIdx.y * KCH;
    float* part = partBase + (size_t)blockIdx.y * (DIM * BATCH);

    // W fp32 load: 8 threads per k-row (32 rows), 16 floats each
    const int wk = tid >> 3;
    const int wn = (tid & 7) * 16;
    const float* wgp = W + (size_t)(kb + wk) * N + n0 + wn;
    const uint32_t wswz = (uint32_t)(wk & 7) << 4;
    const uint32_t wsrow = (uint32_t)wk * 256;

    // A cp.async: 4 threads per m-row, 1 x 16B per polarity
    const int am = tid >> 2;
    const int akc = (tid & 3) * 8;
    const __nv_bfloat16* agpH = actH + (size_t)am * DIM + kb + akc;
    const __nv_bfloat16* agpL = actL + (size_t)am * DIM + kb + akc;
    const uint32_t aoff = (uint32_t)am * 128
                        + (((uint32_t)(akc * 2)) ^ ((uint32_t)(am & 7) << 4));

    const uint32_t arow = (lane & 7) + ((lane >> 3) & 1) * 8;
    const uint32_t ak2  = ((lane >> 4) & 1) * 16;
    const uint32_t aswz = (uint32_t)(lane & 7) << 4;

    const uint32_t brow  = (lane & 7) + ((lane >> 3) & 1) * 8;
    const uint32_t bhalf = ((lane >> 4) & 1) * 8;

    float acc[2][4][4];
    #pragma unroll
    for (int i = 0; i < 2; ++i)
        #pragma unroll
        for (int j = 0; j < 4; ++j)
            #pragma unroll
            for (int q = 0; q < 4; ++q) acc[i][j][q] = 0.f;

    float4 wreg[4];   // FULL next-stage W (16 regs)

    auto loadW = [&](int s) {
        const float* p = wgp + (size_t)(s * 32) * N;
        #pragma unroll
        for (int j = 0; j < 4; ++j)
            wreg[j] = *reinterpret_cast<const float4*>(p + j * 4);
    };
    auto storeW = [&](int buf) {   // pure cvt + STS, no LDG dependence
        const uint32_t bH = s0 + buf * STG32 + wsrow;
        const uint32_t bL = bH + O32_WL;
        #pragma unroll
        for (int j = 0; j < 4; ++j)
            stW_hilo(bH, bL, ((uint32_t)((wn + j * 4) * 2)) ^ wswz, wreg[j]);
    };
    auto issueA = [&](int s, int buf) {
        const uint32_t base = s0 + buf * STG32;
        cp16(base + O32_AH + aoff, agpH + s * 32);
        cp16(base + O32_AL + aoff, agpL + s * 32);
        cp_commit();
    };
    auto compute = [&](int buf) {
        const uint32_t base = s0 + buf * STG32;
        #pragma unroll
        for (int ks = 0; ks < 2; ++ks) {
            uint32_t bh[2][4], bl[2][4];
            #pragma unroll
            for (int nt = 0; nt < 2; ++nt) {
                uint32_t bcol = ((uint32_t)((warpN * 32 + nt * 16 + bhalf) * 2))
                              ^ ((uint32_t)(lane & 7) << 4);
                uint32_t boff = (uint32_t)(ks * 16 + brow) * 256 + bcol;
                ldsm4t(bh[nt], base + boff);
                ldsm4t(bl[nt], base + O32_WL + boff);
            }
            const uint32_t kx = (uint32_t)(ks * 32 + ak2) ^ aswz;
            #pragma unroll
            for (int mt = 0; mt < 2; ++mt) {
                const uint32_t ar = (uint32_t)(warpM * 32 + mt * 16 + arow) * 128
                                  + kx;
                uint32_t ah[4], al[4];
                ldsm4(ah, base + O32_AH + ar);
                ldsm4(al, base + O32_AL + ar);
                #pragma unroll
                for (int nt = 0; nt < 2; ++nt) {
                    mma16816(acc[mt][nt * 2 + 0], ah, bh[nt][0], bh[nt][1]);
                    mma16816(acc[mt][nt * 2 + 1], ah, bh[nt][2], bh[nt][3]);
                    mma16816(acc[mt][nt * 2 + 0], al, bh[nt][0], bh[nt][1]);
                    mma16816(acc[mt][nt * 2 + 1], al, bh[nt][2], bh[nt][3]);
                    mma16816(acc[mt][nt * 2 + 0], ah, bl[nt][0], bl[nt][1]);
                    mma16816(acc[mt][nt * 2 + 1], ah, bl[nt][2], bl[nt][3]);
                }
            }
        }
    };

    // ---- pipeline: storeW(s) is stall-free; loadW(s+1) covered by compute(s)
    issueA(0, 0);
    loadW(0);
    #pragma unroll
    for (int s = 0; s < NST; ++s) {
        const int buf = s & 1;
        storeW(buf);                       // cvt+STS only
        if (s + 1 < NST) loadW(s + 1);     // LDGs; consumed next iter
        cp_wait<0>();
        __syncthreads();
        if (s + 1 < NST) issueA(s + 1, buf ^ 1);
        compute(buf);                      // covers loadW(s+1) latency
    }

    const int g = lane >> 2, tg = lane & 3;
    #pragma unroll
    for (int mt = 0; mt < 2; ++mt)
        #pragma unroll
        for (int nt = 0; nt < 4; ++nt) {
            int feat = n0 + warpN * 32 + nt * 8 + tg * 2;
            int bat  = warpM * 32 + mt * 16 + g;
            float* p = part + (size_t)feat * 64 + bat;
            p[0]      = acc[mt][nt][0];
            p[64]     = acc[mt][nt][1];
            p[8]      = acc[mt][nt][2];
            p[64 + 8] = acc[mt][nt][3];
        }
}

// ---------------------------------------------------------------------------
// L3 GEMM (R12-proven): k64 stages, NT=64, NST=4
// ---------------------------------------------------------------------------
#define RB64      128
#define WB64      (64 * RB64)
#define O64_WL    WB64
#define O64_AH    (2 * WB64)
#define O64_AL    (2 * WB64 + 8192)
#define STG64     (2 * WB64 + 16384)
#define SMEM_K64  (2 * STG64 + 1024)

__global__ void __launch_bounds__(256) gemm_l3(
    const float* __restrict__ W, int N,
    const __nv_bfloat16* __restrict__ actH,
    const __nv_bfloat16* __restrict__ actL,
    float* __restrict__ partBase)
{
    constexpr int NST = 4;
    extern __shared__ char smraw[];
    const uint32_t s0 = (smem_u32(smraw) + 1023) & ~1023u;
    const int tid = threadIdx.x;
    const int warp = tid >> 5, lane = tid & 31;
    const int warpM = warp & 1;
    const int warpN = warp >> 1;
    const int n0 = blockIdx.x * 64;
    const int kb = blockIdx.y * 256;
    float* part = partBase + (size_t)blockIdx.y * (DIM * BATCH);

    const int wk = tid >> 2;
    const int wn = (tid & 3) * 16;
    const float* wgp = W + (size_t)(kb + wk) * N + n0 + wn;
    const uint32_t wswz = (uint32_t)(wk & 7) << 4;
    const uint32_t wsrow = (uint32_t)wk * RB64;

    const int am = tid >> 2;
    const int akb = (tid & 3) * 16;
    const __nv_bfloat16* agpH = actH + (size_t)am * DIM + kb + akb;
    const __nv_bfloat16* agpL = actL + (size_t)am * DIM + kb + akb;
    uint32_t aoffc[2];
    #pragma unroll
    for (int c = 0; c < 2; ++c)
        aoffc[c] = (uint32_t)am * 128
                 + (((uint32_t)(akb * 2 + c * 16)) ^ ((uint32_t)(am & 7) << 4));

    const uint32_t arow = (lane & 7) + ((lane >> 3) & 1) * 8;
    const uint32_t ak2  = ((lane >> 4) & 1) * 16;
    const uint32_t aswz = (uint32_t)(lane & 7) << 4;

    const uint32_t brow  = (lane & 7) + ((lane >> 3) & 1) * 8;
    const uint32_t bhalf = ((lane >> 4) & 1) * 8;

    float acc[2][2][4];
    #pragma unroll
    for (int i = 0; i < 2; ++i)
        #pragma unroll
        for (int j = 0; j < 2; ++j)
            #pragma unroll
            for (int q = 0; q < 4; ++q) acc[i][j][q] = 0.f;

    float4 wreg[4];

    auto loadW = [&](int s) {
        const float* p = wgp + (size_t)s * 64 * N;
        #pragma unroll
        for (int j = 0; j < 4; ++j) {
            int col = n0 + wn + j * 4;
            if (col + 3 < N) {
                wreg[j] = *reinterpret_cast<const float4*>(p + j * 4);
            } else {
                float4 v;
                v.x = (col + 0 < N) ? p[j * 4 + 0] : 0.f;
                v.y = (col + 1 < N) ? p[j * 4 + 1] : 0.f;
                v.z = (col + 2 < N) ? p[j * 4 + 2] : 0.f;
                v.w = (col + 3 < N) ? p[j * 4 + 3] : 0.f;
                wreg[j] = v;
            }
        }
    };
    auto storeW = [&](int buf) {
        const uint32_t bH = s0 + buf * STG64 + wsrow;
        const uint32_t bL = bH + O64_WL;
        #pragma unroll
        for (int j = 0; j < 4; ++j)
            stW_hilo(bH, bL, ((uint32_t)((wn + j * 4) * 2)) ^ wswz, wreg[j]);
    };
    auto issueA = [&](int s, int buf) {
        const uint32_t base = s0 + buf * STG64;
        #pragma unroll
        for (int c = 0; c < 2; ++c) {
            cp16(base + O64_AH + aoffc[c], agpH + s * 64 + c * 8);
            cp16(base + O64_AL + aoffc[c], agpL + s * 64 + c * 8);
        }
        cp_commit();
    };
    auto compute = [&](int buf) {
        const uint32_t base = s0 + buf * STG64;
        #pragma unroll
        for (int ks = 0; ks < 4; ++ks) {
            uint32_t bh[4], bl[4];
            uint32_t bcol = ((uint32_t)((warpN * 16 + bhalf) * 2))
                          ^ ((uint32_t)(lane & 7) << 4);
            uint32_t boff = (uint32_t)(ks * 16 + brow) * RB64 + bcol;
            ldsm4t(bh, base + boff);
            ldsm4t(bl, base + O64_WL + boff);
            const uint32_t kx = (uint32_t)(ks * 32 + ak2) ^ aswz;
            #pragma unroll
            for (int mt = 0; mt < 2; ++mt) {
                const uint32_t ar = (uint32_t)(warpM * 32 + mt * 16 + arow) * 128
                                  + kx;
                uint32_t ah[4], al[4];
                ldsm4(ah, base + O64_AH + ar);
                ldsm4(al, base + O64_AL + ar);
                mma16816(acc[mt][0], ah, bh[0], bh[1]);
                mma16816(acc[mt][1], ah, bh[2], bh[3]);
                mma16816(acc[mt][0], al, bh[0], bh[1]);
                mma16816(acc[mt][1], al, bh[2], bh[3]);
                mma16816(acc[mt][0], ah, bl[0], bl[1]);
                mma16816(acc[mt][1], ah, bl[2], bl[3]);
            }
        }
    };

    issueA(0, 0);
    loadW(0);
    #pragma unroll
    for (int s = 0; s < NST; ++s) {
        const int buf = s & 1;
        storeW(buf);
        if (s + 1 < NST) loadW(s + 1);
        cp_wait<0>();
        __syncthreads();
        if (s + 1 < NST) issueA(s + 1, buf ^ 1);
        compute(buf);
    }

    const int g = lane >> 2, tg = lane & 3;
    #pragma unroll
    for (int mt = 0; mt < 2; ++mt)
        #pragma unroll
        for (int nt = 0; nt < 2; ++nt) {
            int feat = n0 + warpN * 16 + nt * 8 + tg * 2;
            int bat  = warpM * 32 + mt * 16 + g;
            float* p = part + (size_t)feat * 64 + bat;
            p[0]      = acc[mt][nt][0];
            p[64]     = acc[mt][nt][1];
            p[8]      = acc[mt][nt][2];
            p[64 + 8] = acc[mt][nt][3];
        }
}

// ---------------------------------------------------------------------------
// Coalesced transpose-reduces (R11-proven; 8 / 16 splits)
// ---------------------------------------------------------------------------
__global__ void __launch_bounds__(256) reduce_bias_relu_t(
    const float* __restrict__ bias,
    __nv_bfloat16* __restrict__ actH,
    __nv_bfloat16* __restrict__ actL)
{
    __shared__ __nv_bfloat16 tH[16][66], tL[16][66];
    const int t = threadIdx.x;
    const int mb = blockIdx.x * 16;

    {
        const int n  = t & 63;
        const int ml = t >> 6;
        #pragma unroll
        for (int j = 0; j < 4; ++j) {
            int mloc = ml * 4 + j;
            int m = mb + mloc;
            float s = bias[m];
            #pragma unroll
            for (int z = 0; z < 8; ++z)
                s += g_part[z][(size_t)m * 64 + n];
            s = fmaxf(s, 0.f);
            __nv_bfloat16 h = __float2bfloat16(s);
            tH[mloc][n] = h;
            tL[mloc][n] = __float2bfloat16(s - __bfloat162float(h));
        }
    }
    __syncthreads();
    {
        const int m2 = t & 15;
        const int nl = t >> 4;
        #pragma unroll
        for (int j = 0; j < 4; ++j) {
            int n2 = nl * 4 + j;
            size_t o = (size_t)n2 * DIM + mb + m2;
            actH[o] = tH[m2][n2];
            actL[o] = tL[m2][n2];
        }
    }
}

__global__ void __launch_bounds__(256) reduce_out_t(
    const float* __restrict__ b3,
    float* __restrict__ out)
{
    __shared__ float tO[8][66];
    const int t = threadIdx.x;
    const int mb = blockIdx.x * 8;

    #pragma unroll
    for (int i = t; i < 512; i += 256) {
        int mloc = i >> 6;
        int n = i & 63;
        int m = mb + mloc;
        float s = b3[m];
        #pragma unroll
        for (int z = 0; z < 16; ++z)
            s += g_part[z][(size_t)m * 64 + n];
        tO[mloc][n] = s;
    }
    __syncthreads();
    #pragma unroll
    for (int i = t; i < 512; i += 256) {
        int mloc = i & 7;
        int n2 = i >> 3;
        out[(size_t)n2 * OUTN + mb + mloc] = tO[mloc][n2];
    }
}

// ---------------------------------------------------------------------------
// launch
// ---------------------------------------------------------------------------
extern "C" void kernel_launch(void* const* d_in, const int* in_sizes, int n_in,
                              void* d_out, int out_size)
{
    const float* x    = (const float*)d_in[0];
    const float* xa   = (const float*)d_in[1];
    const int*   lens = (const int*)  d_in[2];
    const float* w1   = (const float*)d_in[3];
    const float* b1   = (const float*)d_in[4];
    const float* w2   = (const float*)d_in[5];
    const float* b2   = (const float*)d_in[6];
    const float* w3   = (const float*)d_in[7];
    const float* b3   = (const float*)d_in[8];
    float* out = (float*)d_out;

    __nv_bfloat16 *actH, *actL;
    float* part;
    cudaGetSymbolAddress((void**)&actH, g_actH);
    cudaGetSymbolAddress((void**)&actL, g_actL);
    cudaGetSymbolAddress((void**)&part, g_part);

    cudaFuncSetAttribute(gemm_k32,
                         cudaFuncAttributeMaxDynamicSharedMemorySize, SMEM_K32);
    cudaFuncSetAttribute(gemm_l3,
                         cudaFuncAttributeMaxDynamicSharedMemorySize, SMEM_K64);

    // 1) pool -> act hi/lo (4 rows per warp, MLP 8)
    {
        int warps = (BATCH * DIM) / 4;
        int blocks = (warps * 32 + 255) / 256;
        pool_kernel<<<blocks, 256>>>(x, xa, lens, actH, actL);
    }
    // 2) layer 1: 32 n128-tiles x ksplit 8 (kchunk 512, 16 k32-stages)
    gemm_k32<<<dim3(32, 8), 256, SMEM_K32>>>(w1, actH, actL, part);
    reduce_bias_relu_t<<<256, 256>>>(b1, actH, actL);
    // 3) layer 2
    gemm_k32<<<dim3(32, 8), 256, SMEM_K32>>>(w2, actH, actL, part);
    reduce_bias_relu_t<<<256, 256>>>(b2, actH, actL);
    // 4) layer 3: 16 n64-tiles x ksplit 16 (kchunk 256, 4 k64-stages)
    gemm_l3<<<dim3(16, 16), 256, SMEM_K64>>>(w3, OUTN, actH, actL, part);
    reduce_out_t<<<125, 256>>>(b3, out);
}

// round 16
// speedup vs baseline: 1.1315x; 1.0167x over previous
#include <cuda_runtime.h>
#include <cuda_bf16.h>
#include <float.h>
#include <stdint.h>

// ---------------------------------------------------------------------------
// MVCNN: ragged max-pool -> 3-layer MLP.
// GEMMs via mma.sync.m16n8k16 (bf16 hi/lo split, f32 acc).
// R16 = R15 (proven 111.1) with storeW(s+1) moved AFTER the barrier so each
//       warp's cvt/STS (fma/alu pipes) interleaves with its MMA (tensor pipe).
//       Single-variable change vs R15; one barrier per stage retained.
// ---------------------------------------------------------------------------

#define BATCH 64
#define DIM   4096
#define VIEWS 256
#define OUTN  1000

__device__ __align__(256) __nv_bfloat16 g_actH[BATCH * DIM];
__device__ __align__(256) __nv_bfloat16 g_actL[BATCH * DIM];
__device__ __align__(256) float g_part[16][DIM * BATCH];  // [ksplit][feat][batch]

// ---------------------------------------------------------------------------
// helpers
// ---------------------------------------------------------------------------
__device__ __forceinline__ uint32_t smem_u32(const void* p) {
    uint32_t a;
    asm("{ .reg .u64 t; cvta.to.shared.u64 t, %1; cvt.u32.u64 %0, t; }"
        : "=r"(a) : "l"(p));
    return a;
}
__device__ __forceinline__ void cp16(uint32_t dst, const void* src) {
    asm volatile("cp.async.cg.shared.global [%0], [%1], 16;"
                 :: "r"(dst), "l"(src));
}
__device__ __forceinline__ void cp_commit() {
    asm volatile("cp.async.commit_group;" ::: "memory");
}
template<int N> __device__ __forceinline__ void cp_wait() {
    asm volatile("cp.async.wait_group %0;" :: "n"(N) : "memory");
}
__device__ __forceinline__ void ldsm4(uint32_t* r, uint32_t a) {
    asm volatile("ldmatrix.sync.aligned.m8n8.x4.shared.b16 {%0,%1,%2,%3}, [%4];"
        : "=r"(r[0]), "=r"(r[1]), "=r"(r[2]), "=r"(r[3]) : "r"(a));
}
__device__ __forceinline__ void ldsm4t(uint32_t* r, uint32_t a) {
    asm volatile("ldmatrix.sync.aligned.m8n8.x4.trans.shared.b16 {%0,%1,%2,%3}, [%4];"
        : "=r"(r[0]), "=r"(r[1]), "=r"(r[2]), "=r"(r[3]) : "r"(a));
}
__device__ __forceinline__ void mma16816(float* c, const uint32_t* a,
                                         uint32_t b0, uint32_t b1) {
    asm volatile(
        "mma.sync.aligned.m16n8k16.row.col.f32.bf16.bf16.f32 "
        "{%0,%1,%2,%3}, {%4,%5,%6,%7}, {%8,%9}, {%0,%1,%2,%3};"
        : "+f"(c[0]), "+f"(c[1]), "+f"(c[2]), "+f"(c[3])
        : "r"(a[0]), "r"(a[1]), "r"(a[2]), "r"(a[3]), "r"(b0), "r"(b1));
}
__device__ __forceinline__ void stW_hilo(uint32_t baseH, uint32_t baseL,
                                         uint32_t off, float4 f) {
    uint32_t h01, h23, l01, l23;
    asm("cvt.rn.satfinite.bf16x2.f32 %0, %1, %2;" : "=r"(h01) : "f"(f.y), "f"(f.x));
    asm("cvt.rn.satfinite.bf16x2.f32 %0, %1, %2;" : "=r"(h23) : "f"(f.w), "f"(f.z));
    float l0 = f.x - __uint_as_float(h01 << 16);
    float l1 = f.y - __uint_as_float(h01 & 0xffff0000u);
    float l2 = f.z - __uint_as_float(h23 << 16);
    float l3 = f.w - __uint_as_float(h23 & 0xffff0000u);
    asm("cvt.rn.satfinite.bf16x2.f32 %0, %1, %2;" : "=r"(l01) : "f"(l1), "f"(l0));
    asm("cvt.rn.satfinite.bf16x2.f32 %0, %1, %2;" : "=r"(l23) : "f"(l3), "f"(l2));
    asm volatile("st.shared.v2.b32 [%0], {%1,%2};"
                 :: "r"(baseH + off), "r"(h01), "r"(h23));
    asm volatile("st.shared.v2.b32 [%0], {%1,%2};"
                 :: "r"(baseL + off), "r"(l01), "r"(l23));
}

// ---------------------------------------------------------------------------
// Ragged max-pool -> bf16 hi/lo activations  act[batch][feat]  (R12-proven)
// ---------------------------------------------------------------------------
__global__ void pool_kernel(const float* __restrict__ x,
                            const float* __restrict__ xa,
                            const int*   __restrict__ lens,
                            __nv_bfloat16* __restrict__ actH,
                            __nv_bfloat16* __restrict__ actL)
{
    const int gw   = (blockIdx.x * blockDim.x + threadIdx.x) >> 5;
    const int lane = threadIdx.x & 31;
    const int rg   = lane >> 3;
    const int sub  = lane & 7;
    const int row  = gw * 4 + rg;
    if (row >= BATCH * DIM) return;
    const int b = row >> 12;
    const int d = row & 4095;

    const float* src = (d < 2048)
        ? (x  + ((size_t)(b * 2048 + d)        ) * VIEWS)
        : (xa + ((size_t)(b * 2048 + (d - 2048))) * VIEWS);

    int len = lens[b];
    len = max(1, min(len, VIEWS));

    float m = -FLT_MAX;
    #pragma unroll
    for (int i = 0; i < 8; ++i) {
        const int v0 = sub * 4 + i * 32;
        if (v0 < len) {
            float4 v = *reinterpret_cast<const float4*>(src + v0);
            m = fmaxf(m, v.x);
            if (v0 + 1 < len) m = fmaxf(m, v.y);
            if (v0 + 2 < len) m = fmaxf(m, v.z);
            if (v0 + 3 < len) m = fmaxf(m, v.w);
        }
    }
    #pragma unroll
    for (int o = 4; o; o >>= 1)
        m = fmaxf(m, __shfl_xor_sync(0xffffffffu, m, o));

    if (sub == 0) {
        __nv_bfloat16 h = __float2bfloat16(m);
        actH[row] = h;
        actL[row] = __float2bfloat16(m - __bfloat162float(h));
    }
}

// ---------------------------------------------------------------------------
// L1/L2 GEMM: k32 stages, NT=128, ksplit 8, full W prefetch,
// cvt/STS interleaved with MMA (storeW after barrier).
//   grid (32, 8): n128-tiles x ksplit; kchunk 512 -> NST=16 k32-stages.
// ---------------------------------------------------------------------------
#define STG32     32768
#define O32_WL    8192
#define O32_AH    16384
#define O32_AL    24576
#define SMEM_K32  (2 * STG32 + 1024)

__global__ void __launch_bounds__(256, 2) gemm_k32(
    const float* __restrict__ W,
    const __nv_bfloat16* __restrict__ actH,
    const __nv_bfloat16* __restrict__ actL,
    float* __restrict__ partBase)
{
    constexpr int N   = DIM;
    constexpr int NST = 16;
    constexpr int KCH = NST * 32;     // 512

    extern __shared__ char smraw[];
    const uint32_t s0 = (smem_u32(smraw) + 1023) & ~1023u;
    const int tid = threadIdx.x;
    const int warp = tid >> 5, lane = tid & 31;
    const int warpM = warp & 1;
    const int warpN = warp >> 1;
    const int n0 = blockIdx.x * 128;
    const int kb = blockIdx.y * KCH;
    float* part = partBase + (size_t)blockIdx.y * (DIM * BATCH);

    // W fp32 load: 8 threads per k-row (32 rows), 16 floats each
    const int wk = tid >> 3;
    const int wn = (tid & 7) * 16;
    const float* wgp = W + (size_t)(kb + wk) * N + n0 + wn;
    const uint32_t wswz = (uint32_t)(wk & 7) << 4;
    const uint32_t wsrow = (uint32_t)wk * 256;

    // A cp.async: 4 threads per m-row, 1 x 16B per polarity
    const int am = tid >> 2;
    const int akc = (tid & 3) * 8;
    const __nv_bfloat16* agpH = actH + (size_t)am * DIM + kb + akc;
    const __nv_bfloat16* agpL = actL + (size_t)am * DIM + kb + akc;
    const uint32_t aoff = (uint32_t)am * 128
                        + (((uint32_t)(akc * 2)) ^ ((uint32_t)(am & 7) << 4));

    const uint32_t arow = (lane & 7) + ((lane >> 3) & 1) * 8;
    const uint32_t ak2  = ((lane >> 4) & 1) * 16;
    const uint32_t aswz = (uint32_t)(lane & 7) << 4;

    const uint32_t brow  = (lane & 7) + ((lane >> 3) & 1) * 8;
    const uint32_t bhalf = ((lane >> 4) & 1) * 8;

    float acc[2][4][4];
    #pragma unroll
    for (int i = 0; i < 2; ++i)
        #pragma unroll
        for (int j = 0; j < 4; ++j)
            #pragma unroll
            for (int q = 0; q < 4; ++q) acc[i][j][q] = 0.f;

    float4 wreg[4];   // holds W(stage to be stored next)

    auto loadW = [&](int s) {
        const float* p = wgp + (size_t)(s * 32) * N;
        #pragma unroll
        for (int j = 0; j < 4; ++j)
            wreg[j] = *reinterpret_cast<const float4*>(p + j * 4);
    };
    auto storeW = [&](int buf) {   // pure cvt + STS
        const uint32_t bH = s0 + buf * STG32 + wsrow;
        const uint32_t bL = bH + O32_WL;
        #pragma unroll
        for (int j = 0; j < 4; ++j)
            stW_hilo(bH, bL, ((uint32_t)((wn + j * 4) * 2)) ^ wswz, wreg[j]);
    };
    auto issueA = [&](int s, int buf) {
        const uint32_t base = s0 + buf * STG32;
        cp16(base + O32_AH + aoff, agpH + s * 32);
        cp16(base + O32_AL + aoff, agpL + s * 32);
        cp_commit();
    };
    auto compute = [&](int buf) {
        const uint32_t base = s0 + buf * STG32;
        #pragma unroll
        for (int ks = 0; ks < 2; ++ks) {
            uint32_t bh[2][4], bl[2][4];
            #pragma unroll
            for (int nt = 0; nt < 2; ++nt) {
                uint32_t bcol = ((uint32_t)((warpN * 32 + nt * 16 + bhalf) * 2))
                              ^ ((uint32_t)(lane & 7) << 4);
                uint32_t boff = (uint32_t)(ks * 16 + brow) * 256 + bcol;
                ldsm4t(bh[nt], base + boff);
                ldsm4t(bl[nt], base + O32_WL + boff);
            }
            const uint32_t kx = (uint32_t)(ks * 32 + ak2) ^ aswz;
            #pragma unroll
            for (int mt = 0; mt < 2; ++mt) {
                const uint32_t ar = (uint32_t)(warpM * 32 + mt * 16 + arow) * 128
                                  + kx;
                uint32_t ah[4], al[4];
                ldsm4(ah, base + O32_AH + ar);
                ldsm4(al, base + O32_AL + ar);
                #pragma unroll
                for (int nt = 0; nt < 2; ++nt) {
                    mma16816(acc[mt][nt * 2 + 0], ah, bh[nt][0], bh[nt][1]);
                    mma16816(acc[mt][nt * 2 + 1], ah, bh[nt][2], bh[nt][3]);
                    mma16816(acc[mt][nt * 2 + 0], al, bh[nt][0], bh[nt][1]);
                    mma16816(acc[mt][nt * 2 + 1], al, bh[nt][2], bh[nt][3]);
                    mma16816(acc[mt][nt * 2 + 0], ah, bl[nt][0], bl[nt][1]);
                    mma16816(acc[mt][nt * 2 + 1], ah, bl[nt][2], bl[nt][3]);
                }
            }
        }
    };

    // ---- pipeline: one barrier per stage; storeW(s+1) after the barrier so
    //      cvt/STS interleaves with compute(s) MMAs in the same window.
    //      Hazards: storeW(s+1)->buf^1 ordered vs compute(s-1) readers by the
    //      sync at top of this iter; vs compute(s+1) readers by next sync.
    issueA(0, 0);
    loadW(0);
    storeW(0);          // first use of buf0; ordered by sync in iter 0
    loadW(1);
    #pragma unroll
    for (int s = 0; s < NST; ++s) {
        const int buf = s & 1;
        cp_wait<0>();
        __syncthreads();
        if (s + 1 < NST) {
            issueA(s + 1, buf ^ 1);
            storeW(buf ^ 1);              // cvt+STS of W(s+1), overlaps MMA
            if (s + 2 < NST) loadW(s + 2);
        }
        compute(buf);
    }

    const int g = lane >> 2, tg = lane & 3;
    #pragma unroll
    for (int mt = 0; mt < 2; ++mt)
        #pragma unroll
        for (int nt = 0; nt < 4; ++nt) {
            int feat = n0 + warpN * 32 + nt * 8 + tg * 2;
            int bat  = warpM * 32 + mt * 16 + g;
            float* p = part + (size_t)feat * 64 + bat;
            p[0]      = acc[mt][nt][0];
            p[64]     = acc[mt][nt][1];
            p[8]      = acc[mt][nt][2];
            p[64 + 8] = acc[mt][nt][3];
        }
}

// ---------------------------------------------------------------------------
// L3 GEMM (R15-proven): k64 stages, NT=64, NST=4
// ---------------------------------------------------------------------------
#define RB64      128
#define WB64      (64 * RB64)
#define O64_WL    WB64
#define O64_AH    (2 * WB64)
#define O64_AL    (2 * WB64 + 8192)
#define STG64     (2 * WB64 + 16384)
#define SMEM_K64  (2 * STG64 + 1024)

__global__ void __launch_bounds__(256) gemm_l3(
    const float* __restrict__ W, int N,
    const __nv_bfloat16* __restrict__ actH,
    const __nv_bfloat16* __restrict__ actL,
    float* __restrict__ partBase)
{
    constexpr int NST = 4;
    extern __shared__ char smraw[];
    const uint32_t s0 = (smem_u32(smraw) + 1023) & ~1023u;
    const int tid = threadIdx.x;
    const int warp = tid >> 5, lane = tid & 31;
    const int warpM = warp & 1;
    const int warpN = warp >> 1;
    const int n0 = blockIdx.x * 64;
    const int kb = blockIdx.y * 256;
    float* part = partBase + (size_t)blockIdx.y * (DIM * BATCH);

    const int wk = tid >> 2;
    const int wn = (tid & 3) * 16;
    const float* wgp = W + (size_t)(kb + wk) * N + n0 + wn;
    const uint32_t wswz = (uint32_t)(wk & 7) << 4;
    const uint32_t wsrow = (uint32_t)wk * RB64;

    const int am = tid >> 2;
    const int akb = (tid & 3) * 16;
    const __nv_bfloat16* agpH = actH + (size_t)am * DIM + kb + akb;
    const __nv_bfloat16* agpL = actL + (size_t)am * DIM + kb + akb;
    uint32_t aoffc[2];
    #pragma unroll
    for (int c = 0; c < 2; ++c)
        aoffc[c] = (uint32_t)am * 128
                 + (((uint32_t)(akb * 2 + c * 16)) ^ ((uint32_t)(am & 7) << 4));

    const uint32_t arow = (lane & 7) + ((lane >> 3) & 1) * 8;
    const uint32_t ak2  = ((lane >> 4) & 1) * 16;
    const uint32_t aswz = (uint32_t)(lane & 7) << 4;

    const uint32_t brow  = (lane & 7) + ((lane >> 3) & 1) * 8;
    const uint32_t bhalf = ((lane >> 4) & 1) * 8;

    float acc[2][2][4];
    #pragma unroll
    for (int i = 0; i < 2; ++i)
        #pragma unroll
        for (int j = 0; j < 2; ++j)
            #pragma unroll
            for (int q = 0; q < 4; ++q) acc[i][j][q] = 0.f;

    float4 wreg[4];

    auto loadW = [&](int s) {
        const float* p = wgp + (size_t)s * 64 * N;
        #pragma unroll
        for (int j = 0; j < 4; ++j) {
            int col = n0 + wn + j * 4;
            if (col + 3 < N) {
                wreg[j] = *reinterpret_cast<const float4*>(p + j * 4);
            } else {
                float4 v;
                v.x = (col + 0 < N) ? p[j * 4 + 0] : 0.f;
                v.y = (col + 1 < N) ? p[j * 4 + 1] : 0.f;
                v.z = (col + 2 < N) ? p[j * 4 + 2] : 0.f;
                v.w = (col + 3 < N) ? p[j * 4 + 3] : 0.f;
                wreg[j] = v;
            }
        }
    };
    auto storeW = [&](int buf) {
        const uint32_t bH = s0 + buf * STG64 + wsrow;
        const uint32_t bL = bH + O64_WL;
        #pragma unroll
        for (int j = 0; j < 4; ++j)
            stW_hilo(bH, bL, ((uint32_t)((wn + j * 4) * 2)) ^ wswz, wreg[j]);
    };
    auto issueA = [&](int s, int buf) {
        const uint32_t base = s0 + buf * STG64;
        #pragma unroll
        for (int c = 0; c < 2; ++c) {
            cp16(base + O64_AH + aoffc[c], agpH + s * 64 + c * 8);
            cp16(base + O64_AL + aoffc[c], agpL + s * 64 + c * 8);
        }
        cp_commit();
    };
    auto compute = [&](int buf) {
        const uint32_t base = s0 + buf * STG64;
        #pragma unroll
        for (int ks = 0; ks < 4; ++ks) {
            uint32_t bh[4], bl[4];
            uint32_t bcol = ((uint32_t)((warpN * 16 + bhalf) * 2))
                          ^ ((uint32_t)(lane & 7) << 4);
            uint32_t boff = (uint32_t)(ks * 16 + brow) * RB64 + bcol;
            ldsm4t(bh, base + boff);
            ldsm4t(bl, base + O64_WL + boff);
            const uint32_t kx = (uint32_t)(ks * 32 + ak2) ^ aswz;
            #pragma unroll
            for (int mt = 0; mt < 2; ++mt) {
                const uint32_t ar = (uint32_t)(warpM * 32 + mt * 16 + arow) * 128
                                  + kx;
                uint32_t ah[4], al[4];
                ldsm4(ah, base + O64_AH + ar);
                ldsm4(al, base + O64_AL + ar);
                mma16816(acc[mt][0], ah, bh[0], bh[1]);
                mma16816(acc[mt][1], ah, bh[2], bh[3]);
                mma16816(acc[mt][0], al, bh[0], bh[1]);
                mma16816(acc[mt][1], al, bh[2], bh[3]);
                mma16816(acc[mt][0], ah, bl[0], bl[1]);
                mma16816(acc[mt][1], ah, bl[2], bl[3]);
            }
        }
    };

    issueA(0, 0);
    loadW(0);
    #pragma unroll
    for (int s = 0; s < NST; ++s) {
        const int buf = s & 1;
        storeW(buf);
        if (s + 1 < NST) loadW(s + 1);
        cp_wait<0>();
        __syncthreads();
        if (s + 1 < NST) issueA(s + 1, buf ^ 1);
        compute(buf);
    }

    const int g = lane >> 2, tg = lane & 3;
    #pragma unroll
    for (int mt = 0; mt < 2; ++mt)
        #pragma unroll
        for (int nt = 0; nt < 2; ++nt) {
            int feat = n0 + warpN * 16 + nt * 8 + tg * 2;
            int bat  = warpM * 32 + mt * 16 + g;
            float* p = part + (size_t)feat * 64 + bat;
            p[0]      = acc[mt][nt][0];
            p[64]     = acc[mt][nt][1];
            p[8]      = acc[mt][nt][2];
            p[64 + 8] = acc[mt][nt][3];
        }
}

// ---------------------------------------------------------------------------
// Coalesced transpose-reduces (R11-proven; 8 / 16 splits)
// ---------------------------------------------------------------------------
__global__ void __launch_bounds__(256) reduce_bias_relu_t(
    const float* __restrict__ bias,
    __nv_bfloat16* __restrict__ actH,
    __nv_bfloat16* __restrict__ actL)
{
    __shared__ __nv_bfloat16 tH[16][66], tL[16][66];
    const int t = threadIdx.x;
    const int mb = blockIdx.x * 16;

    {
        const int n  = t & 63;
        const int ml = t >> 6;
        #pragma unroll
        for (int j = 0; j < 4; ++j) {
            int mloc = ml * 4 + j;
            int m = mb + mloc;
            float s = bias[m];
            #pragma unroll
            for (int z = 0; z < 8; ++z)
                s += g_part[z][(size_t)m * 64 + n];
            s = fmaxf(s, 0.f);
            __nv_bfloat16 h = __float2bfloat16(s);
            tH[mloc][n] = h;
            tL[mloc][n] = __float2bfloat16(s - __bfloat162float(h));
        }
    }
    __syncthreads();
    {
        const int m2 = t & 15;
        const int nl = t >> 4;
        #pragma unroll
        for (int j = 0; j < 4; ++j) {
            int n2 = nl * 4 + j;
            size_t o = (size_t)n2 * DIM + mb + m2;
            actH[o] = tH[m2][n2];
            actL[o] = tL[m2][n2];
        }
    }
}

__global__ void __launch_bounds__(256) reduce_out_t(
    const float* __restrict__ b3,
    float* __restrict__ out)
{
    __shared__ float tO[8][66];
    const int t = threadIdx.x;
    const int mb = blockIdx.x * 8;

    #pragma unroll
    for (int i = t; i < 512; i += 256) {
        int mloc = i >> 6;
        int n = i & 63;
        int m = mb + mloc;
        float s = b3[m];
        #pragma unroll
        for (int z = 0; z < 16; ++z)
            s += g_part[z][(size_t)m * 64 + n];
        tO[mloc][n] = s;
    }
    __syncthreads();
    #pragma unroll
    for (int i = t; i < 512; i += 256) {
        int mloc = i & 7;
        int n2 = i >> 3;
        out[(size_t)n2 * OUTN + mb + mloc] = tO[mloc][n2];
    }
}

// ---------------------------------------------------------------------------
// launch
// ---------------------------------------------------------------------------
extern "C" void kernel_launch(void* const* d_in, const int* in_sizes, int n_in,
                              void* d_out, int out_size)
{
    const float* x    = (const float*)d_in[0];
    const float* xa   = (const float*)d_in[1];
    const int*   lens = (const int*)  d_in[2];
    const float* w1   = (const float*)d_in[3];
    const float* b1   = (const float*)d_in[4];
    const float* w2   = (const float*)d_in[5];
    const float* b2   = (const float*)d_in[6];
    const float* w3   = (const float*)d_in[7];
    const float* b3   = (const float*)d_in[8];
    float* out = (float*)d_out;

    __nv_bfloat16 *actH, *actL;
    float* part;
    cudaGetSymbolAddress((void**)&actH, g_actH);
    cudaGetSymbolAddress((void**)&actL, g_actL);
    cudaGetSymbolAddress((void**)&part, g_part);

    cudaFuncSetAttribute(gemm_k32,
                         cudaFuncAttributeMaxDynamicSharedMemorySize, SMEM_K32);
    cudaFuncSetAttribute(gemm_l3,
                         cudaFuncAttributeMaxDynamicSharedMemorySize, SMEM_K64);

    // 1) pool -> act hi/lo (4 rows per warp, MLP 8)
    {
        int warps = (BATCH * DIM) / 4;
        int blocks = (warps * 32 + 255) / 256;
        pool_kernel<<<blocks, 256>>>(x, xa, lens, actH, actL);
    }
    // 2) layer 1: 32 n128-tiles x ksplit 8 (kchunk 512, 16 k32-stages)
    gemm_k32<<<dim3(32, 8), 256, SMEM_K32>>>(w1, actH, actL, part);
    reduce_bias_relu_t<<<256, 256>>>(b1, actH, actL);
    // 3) layer 2
    gemm_k32<<<dim3(32, 8), 256, SMEM_K32>>>(w2, actH, actL, part);
    reduce_bias_relu_t<<<256, 256>>>(b2, actH, actL);
    // 4) layer 3: 16 n64-tiles x ksplit 16 (kchunk 256, 4 k64-stages)
    gemm_l3<<<dim3(16, 16), 256, SMEM_K64>>>(w3, OUTN, actH, actL, part);
    reduce_out_t<<<125, 256>>>(b3, out);
}

// round 17
// speedup vs baseline: 1.1600x; 1.0252x over previous
#include <cuda_runtime.h>
#include <cuda_bf16.h>
#include <float.h>
#include <stdint.h>

// ---------------------------------------------------------------------------
// MVCNN: ragged max-pool -> 3-layer MLP.
// GEMMs via mma.sync.m16n8k16 (bf16 hi/lo split, f32 acc).
// R17 = R16 (proven 109.3) + PDL overlap between dependent kernels
//       (grid-dependency sync placed AFTER each kernel's independent W
//       prefetch) + gemm_l3 ported to the R16 pipeline.
// ---------------------------------------------------------------------------

#define BATCH 64
#define DIM   4096
#define VIEWS 256
#define OUTN  1000

__device__ __align__(256) __nv_bfloat16 g_actH[BATCH * DIM];
__device__ __align__(256) __nv_bfloat16 g_actL[BATCH * DIM];
__device__ __align__(256) float g_part[16][DIM * BATCH];  // [ksplit][feat][batch]

// ---------------------------------------------------------------------------
// helpers
// ---------------------------------------------------------------------------
__device__ __forceinline__ uint32_t smem_u32(const void* p) {
    uint32_t a;
    asm("{ .reg .u64 t; cvta.to.shared.u64 t, %1; cvt.u32.u64 %0, t; }"
        : "=r"(a) : "l"(p));
    return a;
}
__device__ __forceinline__ void cp16(uint32_t dst, const void* src) {
    asm volatile("cp.async.cg.shared.global [%0], [%1], 16;"
                 :: "r"(dst), "l"(src));
}
__device__ __forceinline__ void cp_commit() {
    asm volatile("cp.async.commit_group;" ::: "memory");
}
template<int N> __device__ __forceinline__ void cp_wait() {
    asm volatile("cp.async.wait_group %0;" :: "n"(N) : "memory");
}
__device__ __forceinline__ void ldsm4(uint32_t* r, uint32_t a) {
    asm volatile("ldmatrix.sync.aligned.m8n8.x4.shared.b16 {%0,%1,%2,%3}, [%4];"
        : "=r"(r[0]), "=r"(r[1]), "=r"(r[2]), "=r"(r[3]) : "r"(a));
}
__device__ __forceinline__ void ldsm4t(uint32_t* r, uint32_t a) {
    asm volatile("ldmatrix.sync.aligned.m8n8.x4.trans.shared.b16 {%0,%1,%2,%3}, [%4];"
        : "=r"(r[0]), "=r"(r[1]), "=r"(r[2]), "=r"(r[3]) : "r"(a));
}
__device__ __forceinline__ void mma16816(float* c, const uint32_t* a,
                                         uint32_t b0, uint32_t b1) {
    asm volatile(
        "mma.sync.aligned.m16n8k16.row.col.f32.bf16.bf16.f32 "
        "{%0,%1,%2,%3}, {%4,%5,%6,%7}, {%8,%9}, {%0,%1,%2,%3};"
        : "+f"(c[0]), "+f"(c[1]), "+f"(c[2]), "+f"(c[3])
        : "r"(a[0]), "r"(a[1]), "r"(a[2]), "r"(a[3]), "r"(b0), "r"(b1));
}
__device__ __forceinline__ void stW_hilo(uint32_t baseH, uint32_t baseL,
                                         uint32_t off, float4 f) {
    uint32_t h01, h23, l01, l23;
    asm("cvt.rn.satfinite.bf16x2.f32 %0, %1, %2;" : "=r"(h01) : "f"(f.y), "f"(f.x));
    asm("cvt.rn.satfinite.bf16x2.f32 %0, %1, %2;" : "=r"(h23) : "f"(f.w), "f"(f.z));
    float l0 = f.x - __uint_as_float(h01 << 16);
    float l1 = f.y - __uint_as_float(h01 & 0xffff0000u);
    float l2 = f.z - __uint_as_float(h23 << 16);
    float l3 = f.w - __uint_as_float(h23 & 0xffff0000u);
    asm("cvt.rn.satfinite.bf16x2.f32 %0, %1, %2;" : "=r"(l01) : "f"(l1), "f"(l0));
    asm("cvt.rn.satfinite.bf16x2.f32 %0, %1, %2;" : "=r"(l23) : "f"(l3), "f"(l2));
    asm volatile("st.shared.v2.b32 [%0], {%1,%2};"
                 :: "r"(baseH + off), "r"(h01), "r"(h23));
    asm volatile("st.shared.v2.b32 [%0], {%1,%2};"
                 :: "r"(baseL + off), "r"(l01), "r"(l23));
}

// ---------------------------------------------------------------------------
// Ragged max-pool -> bf16 hi/lo activations  act[batch][feat]  (R12-proven)
// ---------------------------------------------------------------------------
__global__ void pool_kernel(const float* __restrict__ x,
                            const float* __restrict__ xa,
                            const int*   __restrict__ lens,
                            __nv_bfloat16* __restrict__ actH,
                            __nv_bfloat16* __restrict__ actL)
{
    const int gw   = (blockIdx.x * blockDim.x + threadIdx.x) >> 5;
    const int lane = threadIdx.x & 31;
    const int rg   = lane >> 3;
    const int sub  = lane & 7;
    const int row  = gw * 4 + rg;
    if (row >= BATCH * DIM) return;
    const int b = row >> 12;
    const int d = row & 4095;

    const float* src = (d < 2048)
        ? (x  + ((size_t)(b * 2048 + d)        ) * VIEWS)
        : (xa + ((size_t)(b * 2048 + (d - 2048))) * VIEWS);

    int len = lens[b];
    len = max(1, min(len, VIEWS));

    float m = -FLT_MAX;
    #pragma unroll
    for (int i = 0; i < 8; ++i) {
        const int v0 = sub * 4 + i * 32;
        if (v0 < len) {
            float4 v = *reinterpret_cast<const float4*>(src + v0);
            m = fmaxf(m, v.x);
            if (v0 + 1 < len) m = fmaxf(m, v.y);
            if (v0 + 2 < len) m = fmaxf(m, v.z);
            if (v0 + 3 < len) m = fmaxf(m, v.w);
        }
    }
    #pragma unroll
    for (int o = 4; o; o >>= 1)
        m = fmaxf(m, __shfl_xor_sync(0xffffffffu, m, o));

    if (sub == 0) {
        __nv_bfloat16 h = __float2bfloat16(m);
        actH[row] = h;
        actL[row] = __float2bfloat16(m - __bfloat162float(h));
    }
}

// ---------------------------------------------------------------------------
// L1/L2 GEMM: k32 stages, NT=128, ksplit 8, full W prefetch, cvt interleaved
// with MMA. PDL: W prefetch + first storeW happen BEFORE grid-dep sync.
// ---------------------------------------------------------------------------
#define STG32     32768
#define O32_WL    8192
#define O32_AH    16384
#define O32_AL    24576
#define SMEM_K32  (2 * STG32 + 1024)

__global__ void __launch_bounds__(256, 2) gemm_k32(
    const float* __restrict__ W,
    const __nv_bfloat16* __restrict__ actH,
    const __nv_bfloat16* __restrict__ actL,
    float* __restrict__ partBase)
{
    constexpr int N   = DIM;
    constexpr int NST = 16;
    constexpr int KCH = NST * 32;     // 512

    extern __shared__ char smraw[];
    const uint32_t s0 = (smem_u32(smraw) + 1023) & ~1023u;
    const int tid = threadIdx.x;
    const int warp = tid >> 5, lane = tid & 31;
    const int warpM = warp & 1;
    const int warpN = warp >> 1;
    const int n0 = blockIdx.x * 128;
    const int kb = blockIdx.y * KCH;
    float* part = partBase + (size_t)blockIdx.y * (DIM * BATCH);

    const int wk = tid >> 3;
    const int wn = (tid & 7) * 16;
    const float* wgp = W + (size_t)(kb + wk) * N + n0 + wn;
    const uint32_t wswz = (uint32_t)(wk & 7) << 4;
    const uint32_t wsrow = (uint32_t)wk * 256;

    const int am = tid >> 2;
    const int akc = (tid & 3) * 8;
    const __nv_bfloat16* agpH = actH + (size_t)am * DIM + kb + akc;
    const __nv_bfloat16* agpL = actL + (size_t)am * DIM + kb + akc;
    const uint32_t aoff = (uint32_t)am * 128
                        + (((uint32_t)(akc * 2)) ^ ((uint32_t)(am & 7) << 4));

    const uint32_t arow = (lane & 7) + ((lane >> 3) & 1) * 8;
    const uint32_t ak2  = ((lane >> 4) & 1) * 16;
    const uint32_t aswz = (uint32_t)(lane & 7) << 4;

    const uint32_t brow  = (lane & 7) + ((lane >> 3) & 1) * 8;
    const uint32_t bhalf = ((lane >> 4) & 1) * 8;

    float acc[2][4][4];
    #pragma unroll
    for (int i = 0; i < 2; ++i)
        #pragma unroll
        for (int j = 0; j < 4; ++j)
            #pragma unroll
            for (int q = 0; q < 4; ++q) acc[i][j][q] = 0.f;

    float4 wreg[4];

    auto loadW = [&](int s) {
        const float* p = wgp + (size_t)(s * 32) * N;
        #pragma unroll
        for (int j = 0; j < 4; ++j)
            wreg[j] = *reinterpret_cast<const float4*>(p + j * 4);
    };
    auto storeW = [&](int buf) {
        const uint32_t bH = s0 + buf * STG32 + wsrow;
        const uint32_t bL = bH + O32_WL;
        #pragma unroll
        for (int j = 0; j < 4; ++j)
            stW_hilo(bH, bL, ((uint32_t)((wn + j * 4) * 2)) ^ wswz, wreg[j]);
    };
    auto issueA = [&](int s, int buf) {
        const uint32_t base = s0 + buf * STG32;
        cp16(base + O32_AH + aoff, agpH + s * 32);
        cp16(base + O32_AL + aoff, agpL + s * 32);
        cp_commit();
    };
    auto compute = [&](int buf) {
        const uint32_t base = s0 + buf * STG32;
        #pragma unroll
        for (int ks = 0; ks < 2; ++ks) {
            uint32_t bh[2][4], bl[2][4];
            #pragma unroll
            for (int nt = 0; nt < 2; ++nt) {
                uint32_t bcol = ((uint32_t)((warpN * 32 + nt * 16 + bhalf) * 2))
                              ^ ((uint32_t)(lane & 7) << 4);
                uint32_t boff = (uint32_t)(ks * 16 + brow) * 256 + bcol;
                ldsm4t(bh[nt], base + boff);
                ldsm4t(bl[nt], base + O32_WL + boff);
            }
            const uint32_t kx = (uint32_t)(ks * 32 + ak2) ^ aswz;
            #pragma unroll
            for (int mt = 0; mt < 2; ++mt) {
                const uint32_t ar = (uint32_t)(warpM * 32 + mt * 16 + arow) * 128
                                  + kx;
                uint32_t ah[4], al[4];
                ldsm4(ah, base + O32_AH + ar);
                ldsm4(al, base + O32_AL + ar);
                #pragma unroll
                for (int nt = 0; nt < 2; ++nt) {
                    mma16816(acc[mt][nt * 2 + 0], ah, bh[nt][0], bh[nt][1]);
                    mma16816(acc[mt][nt * 2 + 1], ah, bh[nt][2], bh[nt][3]);
                    mma16816(acc[mt][nt * 2 + 0], al, bh[nt][0], bh[nt][1]);
                    mma16816(acc[mt][nt * 2 + 1], al, bh[nt][2], bh[nt][3]);
                    mma16816(acc[mt][nt * 2 + 0], ah, bl[nt][0], bl[nt][1]);
                    mma16816(acc[mt][nt * 2 + 1], ah, bl[nt][2], bl[nt][3]);
                }
            }
        }
    };

    // ---- PDL prologue: W work is independent of predecessor outputs ----
    loadW(0);
    storeW(0);
    loadW(1);
    cudaGridDependencySynchronize();   // act (predecessor output) safe after
    issueA(0, 0);
    #pragma unroll
    for (int s = 0; s < NST; ++s) {
        const int buf = s & 1;
        cp_wait<0>();
        __syncthreads();
        if (s + 1 < NST) {
            issueA(s + 1, buf ^ 1);
            storeW(buf ^ 1);
            if (s + 2 < NST) loadW(s + 2);
        }
        compute(buf);
    }

    const int g = lane >> 2, tg = lane & 3;
    #pragma unroll
    for (int mt = 0; mt < 2; ++mt)
        #pragma unroll
        for (int nt = 0; nt < 4; ++nt) {
            int feat = n0 + warpN * 32 + nt * 8 + tg * 2;
            int bat  = warpM * 32 + mt * 16 + g;
            float* p = part + (size_t)feat * 64 + bat;
            p[0]      = acc[mt][nt][0];
            p[64]     = acc[mt][nt][1];
            p[8]      = acc[mt][nt][2];
            p[64 + 8] = acc[mt][nt][3];
        }
}

// ---------------------------------------------------------------------------
// L3 GEMM: k64 stages, NT=64, NST=4 — ported to R16 pipeline + PDL.
// ---------------------------------------------------------------------------
#define RB64      128
#define WB64      (64 * RB64)
#define O64_WL    WB64
#define O64_AH    (2 * WB64)
#define O64_AL    (2 * WB64 + 8192)
#define STG64     (2 * WB64 + 16384)
#define SMEM_K64  (2 * STG64 + 1024)

__global__ void __launch_bounds__(256) gemm_l3(
    const float* __restrict__ W, int N,
    const __nv_bfloat16* __restrict__ actH,
    const __nv_bfloat16* __restrict__ actL,
    float* __restrict__ partBase)
{
    constexpr int NST = 4;
    extern __shared__ char smraw[];
    const uint32_t s0 = (smem_u32(smraw) + 1023) & ~1023u;
    const int tid = threadIdx.x;
    const int warp = tid >> 5, lane = tid & 31;
    const int warpM = warp & 1;
    const int warpN = warp >> 1;
    const int n0 = blockIdx.x * 64;
    const int kb = blockIdx.y * 256;
    float* part = partBase + (size_t)blockIdx.y * (DIM * BATCH);

    const int wk = tid >> 2;
    const int wn = (tid & 3) * 16;
    const float* wgp = W + (size_t)(kb + wk) * N + n0 + wn;
    const uint32_t wswz = (uint32_t)(wk & 7) << 4;
    const uint32_t wsrow = (uint32_t)wk * RB64;

    const int am = tid >> 2;
    const int akb = (tid & 3) * 16;
    const __nv_bfloat16* agpH = actH + (size_t)am * DIM + kb + akb;
    const __nv_bfloat16* agpL = actL + (size_t)am * DIM + kb + akb;
    uint32_t aoffc[2];
    #pragma unroll
    for (int c = 0; c < 2; ++c)
        aoffc[c] = (uint32_t)am * 128
                 + (((uint32_t)(akb * 2 + c * 16)) ^ ((uint32_t)(am & 7) << 4));

    const uint32_t arow = (lane & 7) + ((lane >> 3) & 1) * 8;
    const uint32_t ak2  = ((lane >> 4) & 1) * 16;
    const uint32_t aswz = (uint32_t)(lane & 7) << 4;

    const uint32_t brow  = (lane & 7) + ((lane >> 3) & 1) * 8;
    const uint32_t bhalf = ((lane >> 4) & 1) * 8;

    float acc[2][2][4];
    #pragma unroll
    for (int i = 0; i < 2; ++i)
        #pragma unroll
        for (int j = 0; j < 2; ++j)
            #pragma unroll
            for (int q = 0; q < 4; ++q) acc[i][j][q] = 0.f;

    float4 wreg[4];

    auto loadW = [&](int s) {
        const float* p = wgp + (size_t)s * 64 * N;
        #pragma unroll
        for (int j = 0; j < 4; ++j) {
            int col = n0 + wn + j * 4;
            if (col + 3 < N) {
                wreg[j] = *reinterpret_cast<const float4*>(p + j * 4);
            } else {
                float4 v;
                v.x = (col + 0 < N) ? p[j * 4 + 0] : 0.f;
                v.y = (col + 1 < N) ? p[j * 4 + 1] : 0.f;
                v.z = (col + 2 < N) ? p[j * 4 + 2] : 0.f;
                v.w = (col + 3 < N) ? p[j * 4 + 3] : 0.f;
                wreg[j] = v;
            }
        }
    };
    auto storeW = [&](int buf) {
        const uint32_t bH = s0 + buf * STG64 + wsrow;
        const uint32_t bL = bH + O64_WL;
        #pragma unroll
        for (int j = 0; j < 4; ++j)
            stW_hilo(bH, bL, ((uint32_t)((wn + j * 4) * 2)) ^ wswz, wreg[j]);
    };
    auto issueA = [&](int s, int buf) {
        const uint32_t base = s0 + buf * STG64;
        #pragma unroll
        for (int c = 0; c < 2; ++c) {
            cp16(base + O64_AH + aoffc[c], agpH + s * 64 + c * 8);
            cp16(base + O64_AL + aoffc[c], agpL + s * 64 + c * 8);
        }
        cp_commit();
    };
    auto compute = [&](int buf) {
        const uint32_t base = s0 + buf * STG64;
        #pragma unroll
        for (int ks = 0; ks < 4; ++ks) {
            uint32_t bh[4], bl[4];
            uint32_t bcol = ((uint32_t)((warpN * 16 + bhalf) * 2))
                          ^ ((uint32_t)(lane & 7) << 4);
            uint32_t boff = (uint32_t)(ks * 16 + brow) * RB64 + bcol;
            ldsm4t(bh, base + boff);
            ldsm4t(bl, base + O64_WL + boff);
            const uint32_t kx = (uint32_t)(ks * 32 + ak2) ^ aswz;
            #pragma unroll
            for (int mt = 0; mt < 2; ++mt) {
                const uint32_t ar = (uint32_t)(warpM * 32 + mt * 16 + arow) * 128
                                  + kx;
                uint32_t ah[4], al[4];
                ldsm4(ah, base + O64_AH + ar);
                ldsm4(al, base + O64_AL + ar);
                mma16816(acc[mt][0], ah, bh[0], bh[1]);
                mma16816(acc[mt][1], ah, bh[2], bh[3]);
                mma16816(acc[mt][0], al, bh[0], bh[1]);
                mma16816(acc[mt][1], al, bh[2], bh[3]);
                mma16816(acc[mt][0], ah, bl[0], bl[1]);
                mma16816(acc[mt][1], ah, bl[2], bl[3]);
            }
        }
    };

    // ---- R16-style pipeline + PDL prologue ----
    loadW(0);
    storeW(0);
    loadW(1);
    cudaGridDependencySynchronize();
    issueA(0, 0);
    #pragma unroll
    for (int s = 0; s < NST; ++s) {
        const int buf = s & 1;
        cp_wait<0>();
        __syncthreads();
        if (s + 1 < NST) {
            issueA(s + 1, buf ^ 1);
            storeW(buf ^ 1);
            if (s + 2 < NST) loadW(s + 2);
        }
        compute(buf);
    }

    const int g = lane >> 2, tg = lane & 3;
    #pragma unroll
    for (int mt = 0; mt < 2; ++mt)
        #pragma unroll
        for (int nt = 0; nt < 2; ++nt) {
            int feat = n0 + warpN * 16 + nt * 8 + tg * 2;
            int bat  = warpM * 32 + mt * 16 + g;
            float* p = part + (size_t)feat * 64 + bat;
            p[0]      = acc[mt][nt][0];
            p[64]     = acc[mt][nt][1];
            p[8]      = acc[mt][nt][2];
            p[64 + 8] = acc[mt][nt][3];
        }
}

// ---------------------------------------------------------------------------
// Coalesced transpose-reduces (R11-proven; 8 / 16 splits) + PDL sync
// ---------------------------------------------------------------------------
__global__ void __launch_bounds__(256) reduce_bias_relu_t(
    const float* __restrict__ bias,
    __nv_bfloat16* __restrict__ actH,
    __nv_bfloat16* __restrict__ actL)
{
    cudaGridDependencySynchronize();
    __shared__ __nv_bfloat16 tH[16][66], tL[16][66];
    const int t = threadIdx.x;
    const int mb = blockIdx.x * 16;

    {
        const int n  = t & 63;
        const int ml = t >> 6;
        #pragma unroll
        for (int j = 0; j < 4; ++j) {
            int mloc = ml * 4 + j;
            int m = mb + mloc;
            float s = bias[m];
            #pragma unroll
            for (int z = 0; z < 8; ++z)
                s += g_part[z][(size_t)m * 64 + n];
            s = fmaxf(s, 0.f);
            __nv_bfloat16 h = __float2bfloat16(s);
            tH[mloc][n] = h;
            tL[mloc][n] = __float2bfloat16(s - __bfloat162float(h));
        }
    }
    __syncthreads();
    {
        const int m2 = t & 15;
        const int nl = t >> 4;
        #pragma unroll
        for (int j = 0; j < 4; ++j) {
            int n2 = nl * 4 + j;
            size_t o = (size_t)n2 * DIM + mb + m2;
            actH[o] = tH[m2][n2];
            actL[o] = tL[m2][n2];
        }
    }
}

__global__ void __launch_bounds__(256) reduce_out_t(
    const float* __restrict__ b3,
    float* __restrict__ out)
{
    cudaGridDependencySynchronize();
    __shared__ float tO[8][66];
    const int t = threadIdx.x;
    const int mb = blockIdx.x * 8;

    #pragma unroll
    for (int i = t; i < 512; i += 256) {
        int mloc = i >> 6;
        int n = i & 63;
        int m = mb + mloc;
        float s = b3[m];
        #pragma unroll
        for (int z = 0; z < 16; ++z)
            s += g_part[z][(size_t)m * 64 + n];
        tO[mloc][n] = s;
    }
    __syncthreads();
    #pragma unroll
    for (int i = t; i < 512; i += 256) {
        int mloc = i & 7;
        int n2 = i >> 3;
        out[(size_t)n2 * OUTN + mb + mloc] = tO[mloc][n2];
    }
}

// ---------------------------------------------------------------------------
// launch (PDL on all dependent kernels)
// ---------------------------------------------------------------------------
template<typename F, typename... Args>
static void launch_pdl(F kern, dim3 grid, dim3 block, size_t smem,
                       Args... args)
{
    cudaLaunchConfig_t cfg = {};
    cfg.gridDim = grid;
    cfg.blockDim = block;
    cfg.dynamicSmemBytes = smem;
    cfg.stream = 0;
    cudaLaunchAttribute at[1];
    at[0].id = cudaLaunchAttributeProgrammaticStreamSerialization;
    at[0].val.programmaticStreamSerializationAllowed = 1;
    cfg.attrs = at;
    cfg.numAttrs = 1;
    cudaLaunchKernelEx(&cfg, kern, args...);
}

extern "C" void kernel_launch(void* const* d_in, const int* in_sizes, int n_in,
                              void* d_out, int out_size)
{
    const float* x    = (const float*)d_in[0];
    const float* xa   = (const float*)d_in[1];
    const int*   lens = (const int*)  d_in[2];
    const float* w1   = (const float*)d_in[3];
    const float* b1   = (const float*)d_in[4];
    const float* w2   = (const float*)d_in[5];
    const float* b2   = (const float*)d_in[6];
    const float* w3   = (const float*)d_in[7];
    const float* b3   = (const float*)d_in[8];
    float* out = (float*)d_out;

    __nv_bfloat16 *actH, *actL;
    float* part;
    cudaGetSymbolAddress((void**)&actH, g_actH);
    cudaGetSymbolAddress((void**)&actL, g_actL);
    cudaGetSymbolAddress((void**)&part, g_part);

    cudaFuncSetAttribute(gemm_k32,
                         cudaFuncAttributeMaxDynamicSharedMemorySize, SMEM_K32);
    cudaFuncSetAttribute(gemm_l3,
                         cudaFuncAttributeMaxDynamicSharedMemorySize, SMEM_K64);

    // 1) pool -> act hi/lo (plain launch)
    {
        int warps = (BATCH * DIM) / 4;
        int blocks = (warps * 32 + 255) / 256;
        pool_kernel<<<blocks, 256>>>(x, xa, lens, actH, actL);
    }
    // 2) layer 1: 32 n128-tiles x ksplit 8 (kchunk 512, 16 k32-stages)
    launch_pdl(gemm_k32, dim3(32, 8), dim3(256), (size_t)SMEM_K32,
               w1, (const __nv_bfloat16*)actH, (const __nv_bfloat16*)actL, part);
    launch_pdl(reduce_bias_relu_t, dim3(256), dim3(256), (size_t)0,
               b1, actH, actL);
    // 3) layer 2
    launch_pdl(gemm_k32, dim3(32, 8), dim3(256), (size_t)SMEM_K32,
               w2, (const __nv_bfloat16*)actH, (const __nv_bfloat16*)actL, part);
    launch_pdl(reduce_bias_relu_t, dim3(256), dim3(256), (size_t)0,
               b2, actH, actL);
    // 4) layer 3: 16 n64-tiles x ksplit 16 (kchunk 256, 4 k64-stages)
    launch_pdl(gemm_l3, dim3(16, 16), dim3(256), (size_t)SMEM_K64,
               w3, OUTN, (const __nv_bfloat16*)actH, (const __nv_bfloat16*)actL,
               part);
    launch_pdl(reduce_out_t, dim3(125), dim3(256), (size_t)0, b3, out);
}